// round 6
// baseline (speedup 1.0000x reference)
#include <cuda_runtime.h>
#include <stdint.h>
#include <math.h>

// HermanModel spiking network — bit-faithful replication of the JAX/XLA-CPU
// reference (partitionable Threefry, XLA ErfInv, eid-ordered scatter chain).
// Step: one block per SM (676 neurons), src-clustered gather, 8B packed
// entries with the 17th src bit recovered from the sorted-tail crossover.

#define NN      100000
#define EE      6400000
#define MAXDEG  192
#define NSTEPS  100

#define NPB     676            // neurons per block; 148*676 = 100048 >= NN
#define TPB     704            // threads per block
#define NB      148            // one block per SM, one wave
#define CAP     45056          // staged edges per block (mean 43264, +8.6 sigma) < 2^16
#define NBUCK   1563           // src buckets of 64

struct __align__(8) Edge  { int src; float w; };
struct __align__(8) GEnt  { unsigned ps; float w; };   // (srclo16<<16)|pos16

// ---- static scratch (no allocs allowed) ----
__device__ int      g_is64;
__device__ unsigned g_thr;                        // filt bit-threshold; ~0u = fallback
__device__ int      g_cnt[NN];
__device__ int      g_deg[NN];
__device__ unsigned g_key[(size_t)MAXDEG * NN];   // packed (eid<<8)|slot
__device__ Edge     g_tmp[(size_t)MAXDEG * NN];
__device__ Edge     g_ell[(size_t)MAXDEG * NN];   // eid-ordered ELL (fallback + fill src)
__device__ unsigned g_lofs[NN];                   // block-local CSR offset
__device__ int      g_m[NB];                      // edges per block
__device__ int      g_cross[NB];                  // first gather idx with src >= 65536
__device__ unsigned g_bcnt[(size_t)NB * NBUCK];   // bucket counts -> bases -> cursors
__device__ GEnt     g_g[(size_t)NB * CAP];        // src-clustered gather list
__device__ float    g_actA[NN];
__device__ float    g_actB[NN];
__device__ float    g_spk[(size_t)NSTEPS * NN];   // [t][i]

// ---------------- Threefry-2x32 (JAX's 20-round cipher) ----------------
__host__ __device__ __forceinline__ unsigned rotl32(unsigned x, int r) {
    return (x << r) | (x >> (32 - r));
}
__host__ __device__ __forceinline__ void tf2x32(unsigned k0, unsigned k1,
                                                unsigned x0, unsigned x1,
                                                unsigned &o0, unsigned &o1)
{
    unsigned k2 = k0 ^ k1 ^ 0x1BD11BDAu;
    x0 += k0; x1 += k1;
#define TF_R(r) { x0 += x1; x1 = rotl32(x1, r); x1 ^= x0; }
#define TF_G1   TF_R(13) TF_R(15) TF_R(26) TF_R(6)
#define TF_G2   TF_R(17) TF_R(29) TF_R(16) TF_R(24)
    TF_G1  x0 += k1; x1 += k2 + 1u;
    TF_G2  x0 += k2; x1 += k0 + 2u;
    TF_G1  x0 += k0; x1 += k1 + 3u;
    TF_G2  x0 += k1; x1 += k2 + 4u;
    TF_G1  x0 += k2; x1 += k0 + 5u;
#undef TF_G1
#undef TF_G2
#undef TF_R
    o0 = x0; o1 = x1;
}

// ---------------- XLA math replication (strict f32, no FMA) ----------------
__device__ __forceinline__ float xla_log1p(float v) {
    if (fabsf(v) < 1e-4f)
        return __fmul_rn(__fadd_rn(__fmul_rn(-0.5f, v), 1.0f), v);
    return (float)log((double)__fadd_rn(v, 1.0f));
}
__device__ __forceinline__ float xla_erfinv(float x) {
    float w = -xla_log1p(-__fmul_rn(x, x));
    float p;
    if (w < 5.0f) {
        w = __fadd_rn(w, -2.5f);
        p =  2.81022636e-08f;
        p = __fadd_rn( 3.43273939e-07f, __fmul_rn(p, w));
        p = __fadd_rn(-3.5233877e-06f,  __fmul_rn(p, w));
        p = __fadd_rn(-4.39150654e-06f, __fmul_rn(p, w));
        p = __fadd_rn( 0.00021858087f,  __fmul_rn(p, w));
        p = __fadd_rn(-0.00125372503f,  __fmul_rn(p, w));
        p = __fadd_rn(-0.00417768164f,  __fmul_rn(p, w));
        p = __fadd_rn( 0.246640727f,    __fmul_rn(p, w));
        p = __fadd_rn( 1.50140941f,     __fmul_rn(p, w));
    } else {
        w = __fadd_rn(sqrtf(w), -3.0f);
        p = -0.000200214257f;
        p = __fadd_rn( 0.000100950558f, __fmul_rn(p, w));
        p = __fadd_rn( 0.00134934322f,  __fmul_rn(p, w));
        p = __fadd_rn(-0.00367342844f,  __fmul_rn(p, w));
        p = __fadd_rn( 0.00573950773f,  __fmul_rn(p, w));
        p = __fadd_rn(-0.0076224613f,   __fmul_rn(p, w));
        p = __fadd_rn( 0.00943887047f,  __fmul_rn(p, w));
        p = __fadd_rn( 1.00167406f,     __fmul_rn(p, w));
        p = __fadd_rn( 2.83297682f,     __fmul_rn(p, w));
    }
    return __fmul_rn(p, x);
}
__device__ __forceinline__ float bits_to_normal(unsigned bits) {
    const float LO = -0.99999994f;
    float f = __fadd_rn(__uint_as_float((bits >> 9) | 0x3F800000u), -1.0f);
    float u = __fadd_rn(__fmul_rn(f, 2.0f), LO);
    u = fmaxf(LO, u);
    return __fmul_rn(1.41421356f, xla_erfinv(u));
}

// ---------------- init: dtype detect + filt bit-threshold ----------------
__global__ void init_k(const void* ei) {
    if (blockIdx.x || threadIdx.x) return;
    const unsigned long long* p = (const unsigned long long*)ei;
    int ok64 = 1;
    for (int k = 0; k < 64; ++k)
        if (p[k] >= (unsigned long long)NN) { ok64 = 0; break; }
    g_is64 = ok64;

    unsigned lo = 0, hi = 1u << 23;
    while (lo < hi) {
        unsigned mid = (lo + hi) >> 1;
        if (bits_to_normal(mid << 9) > 1.5f) hi = mid; else lo = mid + 1;
    }
    unsigned thr = lo, bad = 0;
    unsigned a = (thr > 512u) ? thr - 512u : 0u;
    unsigned b = (thr + 512u < (1u << 23)) ? thr + 512u : (1u << 23);
    for (unsigned m = a; m < b; ++m) {
        bool big = bits_to_normal(m << 9) > 1.5f;
        if (big != (m >= thr)) { bad = 1; break; }
    }
    g_thr = bad ? 0xFFFFFFFFu : thr;
}

// ---------------- prep ----------------
__global__ void prep_zero() {
    size_t i = (size_t)blockIdx.x * blockDim.x + threadIdx.x;
    if (i < NN) g_cnt[i] = 0;
    if (i < (size_t)NB * NBUCK) g_bcnt[i] = 0;
    if (i < NB) g_cross[i] = 0x7FFFFFFF;
}

__global__ void prep_scatter(const void* __restrict__ ei,
                             const float* __restrict__ W)
{
    int e = blockIdx.x * blockDim.x + threadIdx.x;
    if (e >= EE) return;
    int s, d;
    if (g_is64) {
        const long long* p = (const long long*)ei;
        s = (int)p[e]; d = (int)p[(size_t)EE + e];
    } else {
        const int* p = (const int*)ei;
        s = p[e]; d = p[EE + e];
    }
    if ((unsigned)s >= NN || (unsigned)d >= NN) return;
    int slot = atomicAdd(&g_cnt[d], 1);
    if (slot < MAXDEG) {
        size_t p = (size_t)slot * NN + d;
        g_key[p] = ((unsigned)e << 8) | (unsigned)slot;
        Edge ed; ed.src = s; ed.w = W[e];
        g_tmp[p] = ed;
    }
}

// eid-order per neuron (XLA ScatterExpander order) + bucket counting.
// Keys sorted in dynamic SMEM (conflict-free [s*128+tid] layout) to avoid
// the local-memory L1-thrash of a per-thread array.
__global__ void __launch_bounds__(128) prep_sort(const float* __restrict__ act0)
{
    extern __shared__ unsigned skey[];            // MAXDEG * 128 u32 = 96KB
    int tid = threadIdx.x;
    int i = blockIdx.x * blockDim.x + tid;
    if (i >= NN) return;
    int d = g_cnt[i]; if (d > MAXDEG) d = MAXDEG;
    g_deg[i] = d;
    for (int s = 0; s < d; ++s)
        skey[s * 128 + tid] = g_key[(size_t)s * NN + i];
    for (int a = 1; a < d; ++a) {
        unsigned k = skey[a * 128 + tid];
        int b = a - 1;
        while (b >= 0 && skey[b * 128 + tid] > k) {
            skey[(b + 1) * 128 + tid] = skey[b * 128 + tid]; --b;
        }
        skey[(b + 1) * 128 + tid] = k;
    }
    int blk = i / NPB;
    unsigned* bc = &g_bcnt[(size_t)blk * NBUCK];
    for (int s = 0; s < d; ++s) {
        Edge ed = g_tmp[(size_t)(skey[s * 128 + tid] & 0xFFu) * NN + i];
        g_ell[(size_t)s * NN + i] = ed;
        atomicAdd(&bc[(unsigned)ed.src >> 6], 1u);
    }
    g_actA[i] = act0[i];
}

// per-block exclusive scan of degrees -> block-local CSR offsets
__global__ void __launch_bounds__(TPB) prep_csr()
{
    __shared__ unsigned sa[TPB], sb[TPB];
    int blk = blockIdx.x, tid = threadIdx.x;
    int i = blk * NPB + tid;
    unsigned d = (tid < NPB && i < NN) ? (unsigned)g_deg[i] : 0u;
    sa[tid] = d;
    __syncthreads();
    unsigned *in = sa, *out = sb;
    for (int off = 1; off < TPB; off <<= 1) {
        out[tid] = in[tid] + ((tid >= off) ? in[tid - off] : 0u);
        __syncthreads();
        unsigned* t = in; in = out; out = t;
    }
    unsigned incl = in[tid];
    if (tid < NPB && i < NN) g_lofs[i] = incl - d;
    if (tid == TPB - 1) g_m[blk] = (int)incl;
}

// per-block exclusive scan of bucket counts -> bases (reused as cursors)
__global__ void __launch_bounds__(256) prep_bscan()
{
    __shared__ unsigned part[256], pa[256], pb[256];
    int blk = blockIdx.x, tid = threadIdx.x;
    unsigned* c = &g_bcnt[(size_t)blk * NBUCK];
    const int PER = (NBUCK + 255) / 256;   // 7
    unsigned s = 0;
    for (int k = 0; k < PER; ++k) {
        int idx = tid * PER + k;
        if (idx < NBUCK) s += c[idx];
    }
    part[tid] = s; pa[tid] = s;
    __syncthreads();
    unsigned *in = pa, *out = pb;
    for (int off = 1; off < 256; off <<= 1) {
        out[tid] = in[tid] + ((tid >= off) ? in[tid - off] : 0u);
        __syncthreads();
        unsigned* t = in; in = out; out = t;
    }
    unsigned base = in[tid] - part[tid];
    for (int k = 0; k < PER; ++k) {
        int idx = tid * PER + k;
        if (idx < NBUCK) { unsigned v = c[idx]; c[idx] = base; base += v; }
    }
}

// place edges into src-bucket-clustered gather lists; record the crossover
// index (bucket order => src>=65536 is a contiguous tail of the list).
__global__ void __launch_bounds__(128) prep_fill()
{
    int i = blockIdx.x * blockDim.x + threadIdx.x;
    if (i >= NN) return;
    int d = g_deg[i];
    int blk = i / NPB;
    unsigned lo = g_lofs[i];
    unsigned* cur = &g_bcnt[(size_t)blk * NBUCK];
    size_t base = (size_t)blk * CAP;
    for (int s = 0; s < d; ++s) {
        Edge ed = g_ell[(size_t)s * NN + i];
        unsigned idx = atomicAdd(&cur[(unsigned)ed.src >> 6], 1u);
        unsigned pos = lo + (unsigned)s;
        if (idx < CAP && pos < CAP) {
            GEnt g;
            g.ps = (((unsigned)ed.src & 0xFFFFu) << 16) | pos;
            g.w  = ed.w;
            g_g[base + idx] = g;
            if ((unsigned)ed.src >= 65536u)
                atomicMin(&g_cross[blk], (int)idx);
        }
    }
}

// ---------------- fused simulation step ----------------
__global__ void __launch_bounds__(TPB) step_k(
    int t, int parity,
    unsigned kn0, unsigned kn1, unsigned kf0, unsigned kf1)
{
    extern __shared__ float sval[];          // CAP floats = 176KB
    int blk = blockIdx.x;
    const float* actIn  = parity ? g_actB : g_actA;
    float*       actOut = parity ? g_actA : g_actB;
    int m = g_m[blk];
    int cross = g_cross[blk];
    bool staged = (m <= CAP);

    if (staged) {
        const GEnt* gl = &g_g[(size_t)blk * CAP];
        for (int j = threadIdx.x; j < m; j += TPB) {
            GEnt g = gl[j];
            unsigned src = (g.ps >> 16) + ((j >= cross) ? 65536u : 0u);
            sval[g.ps & 0xFFFFu] = __fmul_rn(g.w, __ldg(&actIn[src]));
        }
    }
    __syncthreads();

    int li = threadIdx.x;
    int i = blk * NPB + li;
    if (li < NPB && i < NN) {
        float acc = 0.0f;
        int d = g_deg[i];
        if (staged) {
            unsigned lo = g_lofs[i];
            for (int s = 0; s < d; ++s)
                acc = __fadd_rn(acc, sval[lo + s]);          // eid-ordered chain
        } else {
            for (int s = 0; s < d; ++s) {
                Edge ed = g_ell[(size_t)s * NN + i];
                acc = __fadd_rn(acc, __fmul_rn(ed.w, __ldg(&actIn[ed.src])));
            }
        }

        unsigned b0, b1;
        tf2x32(kf0, kf1, 0u, (unsigned)i, b0, b1);
        unsigned fb = b0 ^ b1;
        unsigned thr = g_thr;
        bool filt = (thr != 0xFFFFFFFFu) ? ((fb >> 9) >= thr)
                                         : (bits_to_normal(fb) > 1.5f);
        float l;
        if (filt) {
            tf2x32(kn0, kn1, 0u, (unsigned)i, b0, b1);
            float noise = __fmul_rn(0.3f, bits_to_normal(b0 ^ b1));
            l = __fadd_rn(__fmul_rn(0.025f, acc),
                          __fmul_rn(0.001f, __fadd_rn(1.0f, noise)));
        } else {
            l = __fadd_rn(__fmul_rn(0.025f, acc), 0.001f);
        }
        float spike = (l > 0.001378f) ? 1.0f : 0.0f;
        float na = __fsub_rn(__fadd_rn(acc, spike),
                             __fmul_rn(__fdiv_rn(acc, 0.01f), 1e-4f));
        g_spk[(size_t)t * NN + i] = spike;
        actOut[i] = na;
    }
}

// ---------------- [t][i] -> [i][t] transpose ----------------
__global__ void trans_k(float* __restrict__ out)
{
    __shared__ float tile[32][33];
    int i0 = blockIdx.x * 32, t0 = blockIdx.y * 32;
    int tr = t0 + threadIdx.y, ic = i0 + threadIdx.x;
    tile[threadIdx.y][threadIdx.x] =
        (tr < NSTEPS && ic < NN) ? g_spk[(size_t)tr * NN + ic] : 0.0f;
    __syncthreads();
    int iw = i0 + threadIdx.y, tw = t0 + threadIdx.x;
    if (iw < NN && tw < NSTEPS)
        out[(size_t)iw * NSTEPS + tw] = tile[threadIdx.x][threadIdx.y];
}

// ---------------- host ----------------
extern "C" void kernel_launch(void* const* d_in, const int* in_sizes, int n_in,
                              void* d_out, int out_size)
{
    const float* act0 = (const float*)d_in[0];
    const float* W    = (const float*)d_in[1];
    const void*  ei   = d_in[2];
    float*       out  = (float*)d_out;

    cudaFuncSetAttribute(step_k, cudaFuncAttributeMaxDynamicSharedMemorySize,
                         CAP * (int)sizeof(float));
    cudaFuncSetAttribute(prep_sort, cudaFuncAttributeMaxDynamicSharedMemorySize,
                         MAXDEG * 128 * (int)sizeof(unsigned));

    init_k      <<<1, 32>>>(ei);
    {
        size_t zn = (size_t)NB * NBUCK;
        prep_zero<<<(int)((zn + 255) / 256), 256>>>();
    }
    prep_scatter<<<(EE + 255) / 256, 256>>>(ei, W);
    prep_sort   <<<(NN + 127) / 128, 128, MAXDEG * 128 * sizeof(unsigned)>>>(act0);
    prep_csr    <<<NB, TPB>>>();
    prep_bscan  <<<NB, 256>>>();
    prep_fill   <<<(NN + 127) / 128, 128>>>();

    for (int t = 0; t < NSTEPS; ++t) {
        unsigned kt0, kt1, n0, n1, f0, f1;
        tf2x32(0u, 42u, 0u, (unsigned)t, kt0, kt1);
        tf2x32(kt0, kt1, 0u, 0u, n0, n1);
        tf2x32(kt0, kt1, 0u, 1u, f0, f1);
        step_k<<<NB, TPB, CAP * sizeof(float)>>>(t, t & 1, n0, n1, f0, f1);
    }
    trans_k<<<dim3((NN + 31) / 32, (NSTEPS + 31) / 32), dim3(32, 32)>>>(out);
}

// round 7
// speedup vs baseline: 1.2530x; 1.2530x over previous
#include <cuda_runtime.h>
#include <stdint.h>
#include <math.h>

// HermanModel spiking network — bit-faithful replication of the JAX/XLA-CPU
// reference (partitionable Threefry, XLA ErfInv, eid-ordered scatter chain).
// Round-5 architecture (NPB=340, 96KB smem, 2 blocks/SM) + fused prep
// (5 launches, so ncu -s5 profiles step_k) + TPB=512.

#define NN      100000
#define EE      6400000
#define MAXDEG  192
#define NSTEPS  100

#define NPB     340            // neurons per block
#define TPB     512            // threads per block (gather uses all, chain uses NPB)
#define NB      295            // ceil(NN/NPB)
#define CAP     24576          // staged edges per block (mean 21760, +19 sigma); < 2^15
#define NBUCK   1563           // src buckets of 64

struct __align__(8) Edge  { int src; float w; };
struct __align__(8) GEnt  { unsigned packed; float w; };   // (src<<15)|pos

// ---- static scratch (no allocs allowed) ----
__device__ int      g_is64;
__device__ unsigned g_thr;                        // filt bit-threshold; ~0u = fallback
__device__ int      g_cnt[NN];
__device__ int      g_deg[NN];
__device__ unsigned g_key[(size_t)MAXDEG * NN];   // packed (eid<<8)|slot
__device__ Edge     g_tmp[(size_t)MAXDEG * NN];
__device__ Edge     g_ell[(size_t)MAXDEG * NN];   // eid-ordered ELL (fallback + fill src)
__device__ unsigned g_lofs[NN];                   // block-local CSR offset
__device__ int      g_m[NB];                      // edges per block
__device__ unsigned g_bcnt[(size_t)NB * NBUCK];   // bucket counts (global histogram)
__device__ GEnt     g_g[(size_t)NB * CAP];        // src-clustered gather list
__device__ float    g_actA[NN];
__device__ float    g_actB[NN];
__device__ float    g_spk[(size_t)NSTEPS * NN];   // [t][i]

// ---------------- Threefry-2x32 (JAX's 20-round cipher) ----------------
__host__ __device__ __forceinline__ unsigned rotl32(unsigned x, int r) {
    return (x << r) | (x >> (32 - r));
}
__host__ __device__ __forceinline__ void tf2x32(unsigned k0, unsigned k1,
                                                unsigned x0, unsigned x1,
                                                unsigned &o0, unsigned &o1)
{
    unsigned k2 = k0 ^ k1 ^ 0x1BD11BDAu;
    x0 += k0; x1 += k1;
#define TF_R(r) { x0 += x1; x1 = rotl32(x1, r); x1 ^= x0; }
#define TF_G1   TF_R(13) TF_R(15) TF_R(26) TF_R(6)
#define TF_G2   TF_R(17) TF_R(29) TF_R(16) TF_R(24)
    TF_G1  x0 += k1; x1 += k2 + 1u;
    TF_G2  x0 += k2; x1 += k0 + 2u;
    TF_G1  x0 += k0; x1 += k1 + 3u;
    TF_G2  x0 += k1; x1 += k2 + 4u;
    TF_G1  x0 += k2; x1 += k0 + 5u;
#undef TF_G1
#undef TF_G2
#undef TF_R
    o0 = x0; o1 = x1;
}

// ---------------- XLA math replication (strict f32, no FMA) ----------------
__device__ __forceinline__ float xla_log1p(float v) {
    if (fabsf(v) < 1e-4f)
        return __fmul_rn(__fadd_rn(__fmul_rn(-0.5f, v), 1.0f), v);
    return (float)log((double)__fadd_rn(v, 1.0f));
}
__device__ __forceinline__ float xla_erfinv(float x) {
    float w = -xla_log1p(-__fmul_rn(x, x));
    float p;
    if (w < 5.0f) {
        w = __fadd_rn(w, -2.5f);
        p =  2.81022636e-08f;
        p = __fadd_rn( 3.43273939e-07f, __fmul_rn(p, w));
        p = __fadd_rn(-3.5233877e-06f,  __fmul_rn(p, w));
        p = __fadd_rn(-4.39150654e-06f, __fmul_rn(p, w));
        p = __fadd_rn( 0.00021858087f,  __fmul_rn(p, w));
        p = __fadd_rn(-0.00125372503f,  __fmul_rn(p, w));
        p = __fadd_rn(-0.00417768164f,  __fmul_rn(p, w));
        p = __fadd_rn( 0.246640727f,    __fmul_rn(p, w));
        p = __fadd_rn( 1.50140941f,     __fmul_rn(p, w));
    } else {
        w = __fadd_rn(sqrtf(w), -3.0f);
        p = -0.000200214257f;
        p = __fadd_rn( 0.000100950558f, __fmul_rn(p, w));
        p = __fadd_rn( 0.00134934322f,  __fmul_rn(p, w));
        p = __fadd_rn(-0.00367342844f,  __fmul_rn(p, w));
        p = __fadd_rn( 0.00573950773f,  __fmul_rn(p, w));
        p = __fadd_rn(-0.0076224613f,   __fmul_rn(p, w));
        p = __fadd_rn( 0.00943887047f,  __fmul_rn(p, w));
        p = __fadd_rn( 1.00167406f,     __fmul_rn(p, w));
        p = __fadd_rn( 2.83297682f,     __fmul_rn(p, w));
    }
    return __fmul_rn(p, x);
}
__device__ __forceinline__ float bits_to_normal(unsigned bits) {
    const float LO = -0.99999994f;
    float f = __fadd_rn(__uint_as_float((bits >> 9) | 0x3F800000u), -1.0f);
    float u = __fadd_rn(__fmul_rn(f, 2.0f), LO);
    u = fmaxf(LO, u);
    return __fmul_rn(1.41421356f, xla_erfinv(u));
}

// ---------------- launch 0: zero + init (dtype detect, filt threshold) ----
__global__ void prep_zero(const void* ei) {
    size_t i = (size_t)blockIdx.x * blockDim.x + threadIdx.x;
    if (i < NN) g_cnt[i] = 0;
    if (i < (size_t)NB * NBUCK) g_bcnt[i] = 0;

    if (blockIdx.x == 0 && threadIdx.x == 0) {
        const unsigned long long* p = (const unsigned long long*)ei;
        int ok64 = 1;
        for (int k = 0; k < 64; ++k)
            if (p[k] >= (unsigned long long)NN) { ok64 = 0; break; }
        g_is64 = ok64;

        unsigned lo = 0, hi = 1u << 23;
        while (lo < hi) {
            unsigned mid = (lo + hi) >> 1;
            if (bits_to_normal(mid << 9) > 1.5f) hi = mid; else lo = mid + 1;
        }
        unsigned thr = lo, bad = 0;
        unsigned a = (thr > 512u) ? thr - 512u : 0u;
        unsigned b = (thr + 512u < (1u << 23)) ? thr + 512u : (1u << 23);
        for (unsigned m = a; m < b; ++m) {
            bool big = bits_to_normal(m << 9) > 1.5f;
            if (big != (m >= thr)) { bad = 1; break; }
        }
        g_thr = bad ? 0xFFFFFFFFu : thr;
    }
}

// ---------------- launch 1: bin edges by dst ----------------
__global__ void prep_scatter(const void* __restrict__ ei,
                             const float* __restrict__ W)
{
    int e = blockIdx.x * blockDim.x + threadIdx.x;
    if (e >= EE) return;
    int s, d;
    if (g_is64) {
        const long long* p = (const long long*)ei;
        s = (int)p[e]; d = (int)p[(size_t)EE + e];
    } else {
        const int* p = (const int*)ei;
        s = p[e]; d = p[EE + e];
    }
    if ((unsigned)s >= NN || (unsigned)d >= NN) return;
    int slot = atomicAdd(&g_cnt[d], 1);
    if (slot < MAXDEG) {
        size_t p = (size_t)slot * NN + d;
        g_key[p] = ((unsigned)e << 8) | (unsigned)slot;
        Edge ed; ed.src = s; ed.w = W[e];
        g_tmp[p] = ed;
    }
}

// ---------------- launch 2: eid-order per neuron + bucket counts ----------
__global__ void __launch_bounds__(128) prep_sort(const float* __restrict__ act0)
{
    int i = blockIdx.x * blockDim.x + threadIdx.x;
    if (i >= NN) return;
    int d = g_cnt[i]; if (d > MAXDEG) d = MAXDEG;
    g_deg[i] = d;
    unsigned keys[MAXDEG];
    for (int s = 0; s < d; ++s)
        keys[s] = g_key[(size_t)s * NN + i];
    for (int a = 1; a < d; ++a) {
        unsigned k = keys[a];
        int b = a - 1;
        while (b >= 0 && keys[b] > k) { keys[b + 1] = keys[b]; --b; }
        keys[b + 1] = k;
    }
    int blk = i / NPB;
    unsigned* bc = &g_bcnt[(size_t)blk * NBUCK];
    for (int s = 0; s < d; ++s) {
        Edge ed = g_tmp[(size_t)(keys[s] & 0xFFu) * NN + i];
        g_ell[(size_t)s * NN + i] = ed;
        atomicAdd(&bc[(unsigned)ed.src >> 6], 1u);
    }
    g_actA[i] = act0[i];
}

// ---------------- launch 3: per-block degree scan -> CSR offsets ----------
__global__ void __launch_bounds__(TPB) prep_csr()
{
    __shared__ unsigned sa[TPB], sb[TPB];
    int blk = blockIdx.x, tid = threadIdx.x;
    int i = blk * NPB + tid;
    unsigned d = (tid < NPB && i < NN) ? (unsigned)g_deg[i] : 0u;
    sa[tid] = d;
    __syncthreads();
    unsigned *in = sa, *out = sb;
    for (int off = 1; off < TPB; off <<= 1) {
        out[tid] = in[tid] + ((tid >= off) ? in[tid - off] : 0u);
        __syncthreads();
        unsigned* t = in; in = out; out = t;
    }
    unsigned incl = in[tid];
    if (tid < NPB && i < NN) g_lofs[i] = incl - d;
    if (tid == TPB - 1) g_m[blk] = (int)incl;
}

// ---------------- launch 4: fused bucket scan + gather-list fill ----------
// CTA blk: scan its own NBUCK counters in smem, then place its neurons'
// edges with smem atomic cursors (bucket-clustered, eid order within bucket
// irrelevant — only the staged positions matter).
__global__ void __launch_bounds__(256) prep_bscan_fill()
{
    __shared__ unsigned cur[NBUCK];
    __shared__ unsigned part[256], pa[256], pb[256];
    int blk = blockIdx.x, tid = threadIdx.x;
    unsigned* c = &g_bcnt[(size_t)blk * NBUCK];
    const int PER = (NBUCK + 255) / 256;   // 7
    unsigned s = 0;
    for (int k = 0; k < PER; ++k) {
        int idx = tid * PER + k;
        if (idx < NBUCK) s += c[idx];
    }
    part[tid] = s; pa[tid] = s;
    __syncthreads();
    unsigned *in = pa, *out = pb;
    for (int off = 1; off < 256; off <<= 1) {
        out[tid] = in[tid] + ((tid >= off) ? in[tid - off] : 0u);
        __syncthreads();
        unsigned* t = in; in = out; out = t;
    }
    unsigned base = in[tid] - part[tid];
    for (int k = 0; k < PER; ++k) {
        int idx = tid * PER + k;
        if (idx < NBUCK) { cur[idx] = base; base += c[idx]; }
    }
    __syncthreads();

    size_t gbase = (size_t)blk * CAP;
    for (int li = tid; li < NPB; li += 256) {
        int i = blk * NPB + li;
        if (i >= NN) break;
        int d = g_deg[i];
        unsigned lo = g_lofs[i];
        for (int s2 = 0; s2 < d; ++s2) {
            Edge ed = g_ell[(size_t)s2 * NN + i];
            unsigned idx = atomicAdd(&cur[(unsigned)ed.src >> 6], 1u);
            unsigned pos = lo + (unsigned)s2;
            if (idx < CAP && pos < CAP) {
                GEnt g; g.packed = ((unsigned)ed.src << 15) | pos; g.w = ed.w;
                g_g[gbase + idx] = g;
            }
        }
    }
}

// ---------------- launches 5..104: fused simulation step ----------------
__global__ void __launch_bounds__(TPB) step_k(
    int t, int parity,
    unsigned kn0, unsigned kn1, unsigned kf0, unsigned kf1)
{
    extern __shared__ float sval[];          // CAP floats = 96KB
    int blk = blockIdx.x;
    const float* actIn  = parity ? g_actB : g_actA;
    float*       actOut = parity ? g_actA : g_actB;
    int m = g_m[blk];
    bool staged = (m <= CAP);

    if (staged) {
        const GEnt* gl = &g_g[(size_t)blk * CAP];
        for (int j = threadIdx.x; j < m; j += TPB) {
            GEnt g = gl[j];
            sval[g.packed & 0x7FFFu] =
                __fmul_rn(g.w, __ldg(&actIn[g.packed >> 15]));
        }
    }
    __syncthreads();

    int li = threadIdx.x;
    int i = blk * NPB + li;
    if (li < NPB && i < NN) {
        float acc = 0.0f;
        int d = g_deg[i];
        if (staged) {
            unsigned lo = g_lofs[i];
            for (int s = 0; s < d; ++s)
                acc = __fadd_rn(acc, sval[lo + s]);          // eid-ordered chain
        } else {
            for (int s = 0; s < d; ++s) {
                Edge ed = g_ell[(size_t)s * NN + i];
                acc = __fadd_rn(acc, __fmul_rn(ed.w, __ldg(&actIn[ed.src])));
            }
        }

        unsigned b0, b1;
        tf2x32(kf0, kf1, 0u, (unsigned)i, b0, b1);
        unsigned fb = b0 ^ b1;
        unsigned thr = g_thr;
        bool filt = (thr != 0xFFFFFFFFu) ? ((fb >> 9) >= thr)
                                         : (bits_to_normal(fb) > 1.5f);
        float l;
        if (filt) {
            tf2x32(kn0, kn1, 0u, (unsigned)i, b0, b1);
            float noise = __fmul_rn(0.3f, bits_to_normal(b0 ^ b1));
            l = __fadd_rn(__fmul_rn(0.025f, acc),
                          __fmul_rn(0.001f, __fadd_rn(1.0f, noise)));
        } else {
            l = __fadd_rn(__fmul_rn(0.025f, acc), 0.001f);
        }
        float spike = (l > 0.001378f) ? 1.0f : 0.0f;
        float na = __fsub_rn(__fadd_rn(acc, spike),
                             __fmul_rn(__fdiv_rn(acc, 0.01f), 1e-4f));
        g_spk[(size_t)t * NN + i] = spike;
        actOut[i] = na;
    }
}

// ---------------- last launch: [t][i] -> [i][t] transpose ----------------
__global__ void trans_k(float* __restrict__ out)
{
    __shared__ float tile[32][33];
    int i0 = blockIdx.x * 32, t0 = blockIdx.y * 32;
    int tr = t0 + threadIdx.y, ic = i0 + threadIdx.x;
    tile[threadIdx.y][threadIdx.x] =
        (tr < NSTEPS && ic < NN) ? g_spk[(size_t)tr * NN + ic] : 0.0f;
    __syncthreads();
    int iw = i0 + threadIdx.y, tw = t0 + threadIdx.x;
    if (iw < NN && tw < NSTEPS)
        out[(size_t)iw * NSTEPS + tw] = tile[threadIdx.x][threadIdx.y];
}

// ---------------- host ----------------
extern "C" void kernel_launch(void* const* d_in, const int* in_sizes, int n_in,
                              void* d_out, int out_size)
{
    const float* act0 = (const float*)d_in[0];
    const float* W    = (const float*)d_in[1];
    const void*  ei   = d_in[2];
    float*       out  = (float*)d_out;

    cudaFuncSetAttribute(step_k, cudaFuncAttributeMaxDynamicSharedMemorySize,
                         CAP * (int)sizeof(float));

    {
        size_t zn = (size_t)NB * NBUCK;
        prep_zero<<<(int)((zn + 255) / 256), 256>>>(ei);           // launch 0
    }
    prep_scatter   <<<(EE + 255) / 256, 256>>>(ei, W);             // launch 1
    prep_sort      <<<(NN + 127) / 128, 128>>>(act0);              // launch 2
    prep_csr       <<<NB, TPB>>>();                                // launch 3
    prep_bscan_fill<<<NB, 256>>>();                                // launch 4

    for (int t = 0; t < NSTEPS; ++t) {                             // launch 5 = step 0
        unsigned kt0, kt1, n0, n1, f0, f1;
        tf2x32(0u, 42u, 0u, (unsigned)t, kt0, kt1);
        tf2x32(kt0, kt1, 0u, 0u, n0, n1);
        tf2x32(kt0, kt1, 0u, 1u, f0, f1);
        step_k<<<NB, TPB, CAP * sizeof(float)>>>(t, t & 1, n0, n1, f0, f1);
    }
    trans_k<<<dim3((NN + 31) / 32, (NSTEPS + 31) / 32), dim3(32, 32)>>>(out);
}

// round 8
// speedup vs baseline: 1.2559x; 1.0023x over previous
#include <cuda_runtime.h>
#include <stdint.h>
#include <math.h>

// HermanModel spiking network — bit-faithful replication of the JAX/XLA-CPU
// reference (partitionable Threefry, XLA ErfInv, eid-ordered scatter chain).
// NPB=340 / 96KB smem / 2 blocks-per-SM architecture. This round:
// +1 CSR padding (kills chain-phase LDS bank-conflict pathology) and
// 16B-vectorized gather-list loads.

#define NN      100000
#define EE      6400000
#define MAXDEG  192
#define NSTEPS  100

#define NPB     340            // neurons per block
#define TPB     512            // threads per block
#define NB      295            // ceil(NN/NPB)
#define CAP     24576          // staged slots per block (mean 22100 incl. pad); < 2^15
#define NBUCK   1563           // src buckets of 64

struct __align__(8)  Edge  { int src; float w; };
struct __align__(8)  GEnt  { unsigned packed; float w; };    // (src<<15)|pos
struct __align__(16) GEnt2 { GEnt a, b; };

// ---- static scratch (no allocs allowed) ----
__device__ int      g_is64;
__device__ unsigned g_thr;                        // filt bit-threshold; ~0u = fallback
__device__ int      g_cnt[NN];
__device__ int      g_deg[NN];
__device__ unsigned g_key[(size_t)MAXDEG * NN];   // packed (eid<<8)|slot
__device__ Edge     g_tmp[(size_t)MAXDEG * NN];
__device__ Edge     g_ell[(size_t)MAXDEG * NN];   // eid-ordered ELL (fallback + fill src)
__device__ unsigned g_lofs[NN];                   // block-local padded CSR offset
__device__ int      g_m[NB];                      // padded slot count per block
__device__ int      g_medge[NB];                  // real edge count per block
__device__ unsigned g_bcnt[(size_t)NB * NBUCK];   // bucket counts (global histogram)
__device__ GEnt     g_g[(size_t)NB * CAP];        // src-clustered gather list
__device__ float    g_actA[NN];
__device__ float    g_actB[NN];
__device__ float    g_spk[(size_t)NSTEPS * NN];   // [t][i]

// ---------------- Threefry-2x32 (JAX's 20-round cipher) ----------------
__host__ __device__ __forceinline__ unsigned rotl32(unsigned x, int r) {
    return (x << r) | (x >> (32 - r));
}
__host__ __device__ __forceinline__ void tf2x32(unsigned k0, unsigned k1,
                                                unsigned x0, unsigned x1,
                                                unsigned &o0, unsigned &o1)
{
    unsigned k2 = k0 ^ k1 ^ 0x1BD11BDAu;
    x0 += k0; x1 += k1;
#define TF_R(r) { x0 += x1; x1 = rotl32(x1, r); x1 ^= x0; }
#define TF_G1   TF_R(13) TF_R(15) TF_R(26) TF_R(6)
#define TF_G2   TF_R(17) TF_R(29) TF_R(16) TF_R(24)
    TF_G1  x0 += k1; x1 += k2 + 1u;
    TF_G2  x0 += k2; x1 += k0 + 2u;
    TF_G1  x0 += k0; x1 += k1 + 3u;
    TF_G2  x0 += k1; x1 += k2 + 4u;
    TF_G1  x0 += k2; x1 += k0 + 5u;
#undef TF_G1
#undef TF_G2
#undef TF_R
    o0 = x0; o1 = x1;
}

// ---------------- XLA math replication (strict f32, no FMA) ----------------
__device__ __forceinline__ float xla_log1p(float v) {
    if (fabsf(v) < 1e-4f)
        return __fmul_rn(__fadd_rn(__fmul_rn(-0.5f, v), 1.0f), v);
    return (float)log((double)__fadd_rn(v, 1.0f));
}
__device__ __forceinline__ float xla_erfinv(float x) {
    float w = -xla_log1p(-__fmul_rn(x, x));
    float p;
    if (w < 5.0f) {
        w = __fadd_rn(w, -2.5f);
        p =  2.81022636e-08f;
        p = __fadd_rn( 3.43273939e-07f, __fmul_rn(p, w));
        p = __fadd_rn(-3.5233877e-06f,  __fmul_rn(p, w));
        p = __fadd_rn(-4.39150654e-06f, __fmul_rn(p, w));
        p = __fadd_rn( 0.00021858087f,  __fmul_rn(p, w));
        p = __fadd_rn(-0.00125372503f,  __fmul_rn(p, w));
        p = __fadd_rn(-0.00417768164f,  __fmul_rn(p, w));
        p = __fadd_rn( 0.246640727f,    __fmul_rn(p, w));
        p = __fadd_rn( 1.50140941f,     __fmul_rn(p, w));
    } else {
        w = __fadd_rn(sqrtf(w), -3.0f);
        p = -0.000200214257f;
        p = __fadd_rn( 0.000100950558f, __fmul_rn(p, w));
        p = __fadd_rn( 0.00134934322f,  __fmul_rn(p, w));
        p = __fadd_rn(-0.00367342844f,  __fmul_rn(p, w));
        p = __fadd_rn( 0.00573950773f,  __fmul_rn(p, w));
        p = __fadd_rn(-0.0076224613f,   __fmul_rn(p, w));
        p = __fadd_rn( 0.00943887047f,  __fmul_rn(p, w));
        p = __fadd_rn( 1.00167406f,     __fmul_rn(p, w));
        p = __fadd_rn( 2.83297682f,     __fmul_rn(p, w));
    }
    return __fmul_rn(p, x);
}
__device__ __forceinline__ float bits_to_normal(unsigned bits) {
    const float LO = -0.99999994f;
    float f = __fadd_rn(__uint_as_float((bits >> 9) | 0x3F800000u), -1.0f);
    float u = __fadd_rn(__fmul_rn(f, 2.0f), LO);
    u = fmaxf(LO, u);
    return __fmul_rn(1.41421356f, xla_erfinv(u));
}

// ---------------- launch 0: zero + init (dtype detect, filt threshold) ----
__global__ void prep_zero(const void* ei) {
    size_t i = (size_t)blockIdx.x * blockDim.x + threadIdx.x;
    if (i < NN) g_cnt[i] = 0;
    if (i < (size_t)NB * NBUCK) g_bcnt[i] = 0;

    if (blockIdx.x == 0 && threadIdx.x == 0) {
        const unsigned long long* p = (const unsigned long long*)ei;
        int ok64 = 1;
        for (int k = 0; k < 64; ++k)
            if (p[k] >= (unsigned long long)NN) { ok64 = 0; break; }
        g_is64 = ok64;

        unsigned lo = 0, hi = 1u << 23;
        while (lo < hi) {
            unsigned mid = (lo + hi) >> 1;
            if (bits_to_normal(mid << 9) > 1.5f) hi = mid; else lo = mid + 1;
        }
        unsigned thr = lo, bad = 0;
        unsigned a = (thr > 512u) ? thr - 512u : 0u;
        unsigned b = (thr + 512u < (1u << 23)) ? thr + 512u : (1u << 23);
        for (unsigned m = a; m < b; ++m) {
            bool big = bits_to_normal(m << 9) > 1.5f;
            if (big != (m >= thr)) { bad = 1; break; }
        }
        g_thr = bad ? 0xFFFFFFFFu : thr;
    }
}

// ---------------- launch 1: bin edges by dst ----------------
__global__ void prep_scatter(const void* __restrict__ ei,
                             const float* __restrict__ W)
{
    int e = blockIdx.x * blockDim.x + threadIdx.x;
    if (e >= EE) return;
    int s, d;
    if (g_is64) {
        const long long* p = (const long long*)ei;
        s = (int)p[e]; d = (int)p[(size_t)EE + e];
    } else {
        const int* p = (const int*)ei;
        s = p[e]; d = p[EE + e];
    }
    if ((unsigned)s >= NN || (unsigned)d >= NN) return;
    int slot = atomicAdd(&g_cnt[d], 1);
    if (slot < MAXDEG) {
        size_t p = (size_t)slot * NN + d;
        g_key[p] = ((unsigned)e << 8) | (unsigned)slot;
        Edge ed; ed.src = s; ed.w = W[e];
        g_tmp[p] = ed;
    }
}

// ---------------- launch 2: eid-order per neuron + bucket counts ----------
__global__ void __launch_bounds__(128) prep_sort(const float* __restrict__ act0)
{
    int i = blockIdx.x * blockDim.x + threadIdx.x;
    if (i >= NN) return;
    int d = g_cnt[i]; if (d > MAXDEG) d = MAXDEG;
    g_deg[i] = d;
    unsigned keys[MAXDEG];
    for (int s = 0; s < d; ++s)
        keys[s] = g_key[(size_t)s * NN + i];
    for (int a = 1; a < d; ++a) {
        unsigned k = keys[a];
        int b = a - 1;
        while (b >= 0 && keys[b] > k) { keys[b + 1] = keys[b]; --b; }
        keys[b + 1] = k;
    }
    int blk = i / NPB;
    unsigned* bc = &g_bcnt[(size_t)blk * NBUCK];
    for (int s = 0; s < d; ++s) {
        Edge ed = g_tmp[(size_t)(keys[s] & 0xFFu) * NN + i];
        g_ell[(size_t)s * NN + i] = ed;
        atomicAdd(&bc[(unsigned)ed.src >> 6], 1u);
    }
    g_actA[i] = act0[i];
}

// ---------------- launch 3: per-block scan of (deg+1) -> padded CSR -------
// +1 pad per neuron: adjacent neurons' offsets differ by deg+1 (~65), which
// is 1 mod 32 — decorrelates smem banks in the chain phase.
__global__ void __launch_bounds__(TPB) prep_csr()
{
    __shared__ unsigned sa[TPB], sb[TPB];
    int blk = blockIdx.x, tid = threadIdx.x;
    int i = blk * NPB + tid;
    unsigned d = (tid < NPB && i < NN) ? (unsigned)(g_deg[i] + 1) : 0u;
    sa[tid] = d;
    __syncthreads();
    unsigned *in = sa, *out = sb;
    for (int off = 1; off < TPB; off <<= 1) {
        out[tid] = in[tid] + ((tid >= off) ? in[tid - off] : 0u);
        __syncthreads();
        unsigned* t = in; in = out; out = t;
    }
    unsigned incl = in[tid];
    if (tid < NPB && i < NN) g_lofs[i] = incl - d;
    if (tid == TPB - 1) g_m[blk] = (int)incl;
}

// ---------------- launch 4: fused bucket scan + gather-list fill ----------
__global__ void __launch_bounds__(256) prep_bscan_fill()
{
    __shared__ unsigned cur[NBUCK];
    __shared__ unsigned part[256], pa[256], pb[256];
    int blk = blockIdx.x, tid = threadIdx.x;
    unsigned* c = &g_bcnt[(size_t)blk * NBUCK];
    const int PER = (NBUCK + 255) / 256;   // 7
    unsigned s = 0;
    for (int k = 0; k < PER; ++k) {
        int idx = tid * PER + k;
        if (idx < NBUCK) s += c[idx];
    }
    part[tid] = s; pa[tid] = s;
    __syncthreads();
    unsigned *in = pa, *out = pb;
    for (int off = 1; off < 256; off <<= 1) {
        out[tid] = in[tid] + ((tid >= off) ? in[tid - off] : 0u);
        __syncthreads();
        unsigned* t = in; in = out; out = t;
    }
    if (tid == 255) g_medge[blk] = (int)in[255];   // real edge count
    unsigned base = in[tid] - part[tid];
    for (int k = 0; k < PER; ++k) {
        int idx = tid * PER + k;
        if (idx < NBUCK) { cur[idx] = base; base += c[idx]; }
    }
    __syncthreads();

    size_t gbase = (size_t)blk * CAP;
    for (int li = tid; li < NPB; li += 256) {
        int i = blk * NPB + li;
        if (i >= NN) break;
        int d = g_deg[i];
        unsigned lo = g_lofs[i];
        for (int s2 = 0; s2 < d; ++s2) {
            Edge ed = g_ell[(size_t)s2 * NN + i];
            unsigned idx = atomicAdd(&cur[(unsigned)ed.src >> 6], 1u);
            unsigned pos = lo + (unsigned)s2;
            if (idx < CAP && pos < CAP) {
                GEnt g; g.packed = ((unsigned)ed.src << 15) | pos; g.w = ed.w;
                g_g[gbase + idx] = g;
            }
        }
    }
}

// ---------------- launches 5..104: fused simulation step ----------------
__global__ void __launch_bounds__(TPB) step_k(
    int t, int parity,
    unsigned kn0, unsigned kn1, unsigned kf0, unsigned kf1)
{
    extern __shared__ float sval[];          // CAP floats = 96KB
    int blk = blockIdx.x;
    const float* actIn  = parity ? g_actB : g_actA;
    float*       actOut = parity ? g_actA : g_actB;
    int mpad = g_m[blk];
    int me   = g_medge[blk];
    bool staged = (mpad <= CAP && me <= CAP);

    if (staged) {
        const GEnt2* gl2 = (const GEnt2*)&g_g[(size_t)blk * CAP];
        int mp = me >> 1;                     // pairs
        for (int j = threadIdx.x; j < mp; j += TPB) {
            GEnt2 g2 = gl2[j];                // 16B vector load
            sval[g2.a.packed & 0x7FFFu] =
                __fmul_rn(g2.a.w, __ldg(&actIn[g2.a.packed >> 15]));
            sval[g2.b.packed & 0x7FFFu] =
                __fmul_rn(g2.b.w, __ldg(&actIn[g2.b.packed >> 15]));
        }
        if ((me & 1) && threadIdx.x == 0) {   // odd tail
            GEnt g = g_g[(size_t)blk * CAP + (me - 1)];
            sval[g.packed & 0x7FFFu] =
                __fmul_rn(g.w, __ldg(&actIn[g.packed >> 15]));
        }
    }
    __syncthreads();

    int li = threadIdx.x;
    int i = blk * NPB + li;
    if (li < NPB && i < NN) {
        float acc = 0.0f;
        int d = g_deg[i];
        if (staged) {
            unsigned lo = g_lofs[i];
            #pragma unroll 8
            for (int s = 0; s < d; ++s)
                acc = __fadd_rn(acc, sval[lo + s]);          // eid-ordered chain
        } else {
            for (int s = 0; s < d; ++s) {
                Edge ed = g_ell[(size_t)s * NN + i];
                acc = __fadd_rn(acc, __fmul_rn(ed.w, __ldg(&actIn[ed.src])));
            }
        }

        unsigned b0, b1;
        tf2x32(kf0, kf1, 0u, (unsigned)i, b0, b1);
        unsigned fb = b0 ^ b1;
        unsigned thr = g_thr;
        bool filt = (thr != 0xFFFFFFFFu) ? ((fb >> 9) >= thr)
                                         : (bits_to_normal(fb) > 1.5f);
        float l;
        if (filt) {
            tf2x32(kn0, kn1, 0u, (unsigned)i, b0, b1);
            float noise = __fmul_rn(0.3f, bits_to_normal(b0 ^ b1));
            l = __fadd_rn(__fmul_rn(0.025f, acc),
                          __fmul_rn(0.001f, __fadd_rn(1.0f, noise)));
        } else {
            l = __fadd_rn(__fmul_rn(0.025f, acc), 0.001f);
        }
        float spike = (l > 0.001378f) ? 1.0f : 0.0f;
        float na = __fsub_rn(__fadd_rn(acc, spike),
                             __fmul_rn(__fdiv_rn(acc, 0.01f), 1e-4f));
        g_spk[(size_t)t * NN + i] = spike;
        actOut[i] = na;
    }
}

// ---------------- last launch: [t][i] -> [i][t] transpose ----------------
__global__ void trans_k(float* __restrict__ out)
{
    __shared__ float tile[32][33];
    int i0 = blockIdx.x * 32, t0 = blockIdx.y * 32;
    int tr = t0 + threadIdx.y, ic = i0 + threadIdx.x;
    tile[threadIdx.y][threadIdx.x] =
        (tr < NSTEPS && ic < NN) ? g_spk[(size_t)tr * NN + ic] : 0.0f;
    __syncthreads();
    int iw = i0 + threadIdx.y, tw = t0 + threadIdx.x;
    if (iw < NN && tw < NSTEPS)
        out[(size_t)iw * NSTEPS + tw] = tile[threadIdx.x][threadIdx.y];
}

// ---------------- host ----------------
extern "C" void kernel_launch(void* const* d_in, const int* in_sizes, int n_in,
                              void* d_out, int out_size)
{
    const float* act0 = (const float*)d_in[0];
    const float* W    = (const float*)d_in[1];
    const void*  ei   = d_in[2];
    float*       out  = (float*)d_out;

    cudaFuncSetAttribute(step_k, cudaFuncAttributeMaxDynamicSharedMemorySize,
                         CAP * (int)sizeof(float));

    {
        size_t zn = (size_t)NB * NBUCK;
        prep_zero<<<(int)((zn + 255) / 256), 256>>>(ei);           // launch 0
    }
    prep_scatter   <<<(EE + 255) / 256, 256>>>(ei, W);             // launch 1
    prep_sort      <<<(NN + 127) / 128, 128>>>(act0);              // launch 2
    prep_csr       <<<NB, TPB>>>();                                // launch 3
    prep_bscan_fill<<<NB, 256>>>();                                // launch 4

    for (int t = 0; t < NSTEPS; ++t) {
        unsigned kt0, kt1, n0, n1, f0, f1;
        tf2x32(0u, 42u, 0u, (unsigned)t, kt0, kt1);
        tf2x32(kt0, kt1, 0u, 0u, n0, n1);
        tf2x32(kt0, kt1, 0u, 1u, f0, f1);
        step_k<<<NB, TPB, CAP * sizeof(float)>>>(t, t & 1, n0, n1, f0, f1);
    }
    trans_k<<<dim3((NN + 31) / 32, (NSTEPS + 31) / 32), dim3(32, 32)>>>(out);
}

// round 9
// speedup vs baseline: 1.2644x; 1.0067x over previous
#include <cuda_runtime.h>
#include <stdint.h>
#include <math.h>

// HermanModel spiking network — bit-faithful replication of the JAX/XLA-CPU
// reference (partitionable Threefry, XLA ErfInv, eid-ordered scatter chain).
// This round: prep overhaul — warp-shuffle eid-ranking replaces the insertion
// sort; single 16B binned records; fused rank+fill. step_k unchanged.

#define NN      100000
#define EE      6400000
#define MAXDEG  192
#define NSTEPS  100

#define NPB     340            // neurons per step-block
#define TPB     512            // step_k / csr threads
#define NB      295            // ceil(NN/NPB)
#define CAP     24576          // staged slots per block; < 2^15
#define NBUCK   1563           // src buckets of 64

struct __align__(8)  GEnt  { unsigned packed; float w; };    // (src<<15)|pos

// ---- static scratch (no allocs allowed) ----
__device__ int      g_is64;
__device__ unsigned g_thr;                        // filt bit-threshold; ~0u = fallback
__device__ int      g_cnt[NN];
__device__ int      g_deg[NN];
__device__ uint4    g_tmpE[(size_t)MAXDEG * NN];  // {src, w_bits, eid, 0} row-major [i*192+s]
__device__ unsigned g_lofs[NN];                   // block-local padded CSR offset
__device__ int      g_m[NB];                      // padded slot count per block
__device__ int      g_medge[NB];                  // real edge count per block
__device__ unsigned g_bcnt[(size_t)NB * NBUCK];   // bucket counts per step-block
__device__ GEnt     g_g[(size_t)NB * CAP];        // src-clustered gather list
__device__ float    g_actA[NN];
__device__ float    g_actB[NN];
__device__ float    g_spk[(size_t)NSTEPS * NN];   // [t][i]

// ---------------- Threefry-2x32 (JAX's 20-round cipher) ----------------
__host__ __device__ __forceinline__ unsigned rotl32(unsigned x, int r) {
    return (x << r) | (x >> (32 - r));
}
__host__ __device__ __forceinline__ void tf2x32(unsigned k0, unsigned k1,
                                                unsigned x0, unsigned x1,
                                                unsigned &o0, unsigned &o1)
{
    unsigned k2 = k0 ^ k1 ^ 0x1BD11BDAu;
    x0 += k0; x1 += k1;
#define TF_R(r) { x0 += x1; x1 = rotl32(x1, r); x1 ^= x0; }
#define TF_G1   TF_R(13) TF_R(15) TF_R(26) TF_R(6)
#define TF_G2   TF_R(17) TF_R(29) TF_R(16) TF_R(24)
    TF_G1  x0 += k1; x1 += k2 + 1u;
    TF_G2  x0 += k2; x1 += k0 + 2u;
    TF_G1  x0 += k0; x1 += k1 + 3u;
    TF_G2  x0 += k1; x1 += k2 + 4u;
    TF_G1  x0 += k2; x1 += k0 + 5u;
#undef TF_G1
#undef TF_G2
#undef TF_R
    o0 = x0; o1 = x1;
}

// ---------------- XLA math replication (strict f32, no FMA) ----------------
__device__ __forceinline__ float xla_log1p(float v) {
    if (fabsf(v) < 1e-4f)
        return __fmul_rn(__fadd_rn(__fmul_rn(-0.5f, v), 1.0f), v);
    return (float)log((double)__fadd_rn(v, 1.0f));
}
__device__ __forceinline__ float xla_erfinv(float x) {
    float w = -xla_log1p(-__fmul_rn(x, x));
    float p;
    if (w < 5.0f) {
        w = __fadd_rn(w, -2.5f);
        p =  2.81022636e-08f;
        p = __fadd_rn( 3.43273939e-07f, __fmul_rn(p, w));
        p = __fadd_rn(-3.5233877e-06f,  __fmul_rn(p, w));
        p = __fadd_rn(-4.39150654e-06f, __fmul_rn(p, w));
        p = __fadd_rn( 0.00021858087f,  __fmul_rn(p, w));
        p = __fadd_rn(-0.00125372503f,  __fmul_rn(p, w));
        p = __fadd_rn(-0.00417768164f,  __fmul_rn(p, w));
        p = __fadd_rn( 0.246640727f,    __fmul_rn(p, w));
        p = __fadd_rn( 1.50140941f,     __fmul_rn(p, w));
    } else {
        w = __fadd_rn(sqrtf(w), -3.0f);
        p = -0.000200214257f;
        p = __fadd_rn( 0.000100950558f, __fmul_rn(p, w));
        p = __fadd_rn( 0.00134934322f,  __fmul_rn(p, w));
        p = __fadd_rn(-0.00367342844f,  __fmul_rn(p, w));
        p = __fadd_rn( 0.00573950773f,  __fmul_rn(p, w));
        p = __fadd_rn(-0.0076224613f,   __fmul_rn(p, w));
        p = __fadd_rn( 0.00943887047f,  __fmul_rn(p, w));
        p = __fadd_rn( 1.00167406f,     __fmul_rn(p, w));
        p = __fadd_rn( 2.83297682f,     __fmul_rn(p, w));
    }
    return __fmul_rn(p, x);
}
__device__ __forceinline__ float bits_to_normal(unsigned bits) {
    const float LO = -0.99999994f;
    float f = __fadd_rn(__uint_as_float((bits >> 9) | 0x3F800000u), -1.0f);
    float u = __fadd_rn(__fmul_rn(f, 2.0f), LO);
    u = fmaxf(LO, u);
    return __fmul_rn(1.41421356f, xla_erfinv(u));
}

// ---------------- launch 0: zero + init (dtype detect, filt threshold) ----
__global__ void prep_zero(const void* ei) {
    size_t i = (size_t)blockIdx.x * blockDim.x + threadIdx.x;
    if (i < NN) g_cnt[i] = 0;
    if (i < (size_t)NB * NBUCK) g_bcnt[i] = 0;

    if (blockIdx.x == 0 && threadIdx.x == 0) {
        const unsigned long long* p = (const unsigned long long*)ei;
        int ok64 = 1;
        for (int k = 0; k < 64; ++k)
            if (p[k] >= (unsigned long long)NN) { ok64 = 0; break; }
        g_is64 = ok64;

        unsigned lo = 0, hi = 1u << 23;
        while (lo < hi) {
            unsigned mid = (lo + hi) >> 1;
            if (bits_to_normal(mid << 9) > 1.5f) hi = mid; else lo = mid + 1;
        }
        unsigned thr = lo, bad = 0;
        unsigned a = (thr > 512u) ? thr - 512u : 0u;
        unsigned b = (thr + 512u < (1u << 23)) ? thr + 512u : (1u << 23);
        for (unsigned m = a; m < b; ++m) {
            bool big = bits_to_normal(m << 9) > 1.5f;
            if (big != (m >= thr)) { bad = 1; break; }
        }
        g_thr = bad ? 0xFFFFFFFFu : thr;
    }
}

// ---------------- launch 1: bin edges (16B record) + bucket counts --------
__global__ void prep_scatter(const void* __restrict__ ei,
                             const float* __restrict__ W)
{
    int e = blockIdx.x * blockDim.x + threadIdx.x;
    if (e >= EE) return;
    int s, d;
    if (g_is64) {
        const long long* p = (const long long*)ei;
        s = (int)p[e]; d = (int)p[(size_t)EE + e];
    } else {
        const int* p = (const int*)ei;
        s = p[e]; d = p[EE + e];
    }
    if ((unsigned)s >= NN || (unsigned)d >= NN) return;
    int slot = atomicAdd(&g_cnt[d], 1);
    if (slot < MAXDEG) {
        g_tmpE[(size_t)d * MAXDEG + slot] =
            make_uint4((unsigned)s, __float_as_uint(W[e]), (unsigned)e, 0u);
        int blk = d / NPB;
        atomicAdd(&g_bcnt[(size_t)blk * NBUCK + ((unsigned)s >> 6)], 1u);
    }
}

// ---------------- launch 2: per-block scan of (deg+1) -> padded CSR -------
__global__ void __launch_bounds__(TPB) prep_csr(const float* __restrict__ act0)
{
    __shared__ unsigned sa[TPB], sb[TPB];
    int blk = blockIdx.x, tid = threadIdx.x;
    int i = blk * NPB + tid;
    unsigned dd = 0u;
    if (tid < NPB && i < NN) {
        int c = g_cnt[i]; if (c > MAXDEG) c = MAXDEG;
        g_deg[i] = c;
        g_actA[i] = act0[i];
        dd = (unsigned)(c + 1);
    }
    sa[tid] = dd;
    __syncthreads();
    unsigned *in = sa, *out = sb;
    for (int off = 1; off < TPB; off <<= 1) {
        out[tid] = in[tid] + ((tid >= off) ? in[tid - off] : 0u);
        __syncthreads();
        unsigned* t = in; in = out; out = t;
    }
    unsigned incl = in[tid];
    if (tid < NPB && i < NN) g_lofs[i] = incl - dd;
    if (tid == TPB - 1) g_m[blk] = (int)incl;
}

// ---------------- launch 3: fused bucket-scan + rank + fill ----------------
// One 1024-thread CTA per step-block. Phase A: scan this block's NBUCK
// counters into smem cursors. Phase B: warp-per-neuron shuffle ranking by
// eid (rank_s = #{eid' < eid_s}) and direct GEnt emission (pos = lofs+rank).
__global__ void __launch_bounds__(1024) prep_rankfill()
{
    __shared__ unsigned cur[NBUCK];
    __shared__ unsigned part[1024], pa[1024], pb[1024];
    int blk = blockIdx.x, tid = threadIdx.x;
    int wid = tid >> 5, lane = tid & 31;
    unsigned* c = &g_bcnt[(size_t)blk * NBUCK];

    const int PER = (NBUCK + 1023) / 1024;   // 2
    unsigned s0 = 0;
    for (int k = 0; k < PER; ++k) {
        int idx = tid * PER + k;
        if (idx < NBUCK) s0 += c[idx];
    }
    part[tid] = s0; pa[tid] = s0;
    __syncthreads();
    unsigned *in = pa, *out = pb;
    for (int off = 1; off < 1024; off <<= 1) {
        out[tid] = in[tid] + ((tid >= off) ? in[tid - off] : 0u);
        __syncthreads();
        unsigned* t = in; in = out; out = t;
    }
    if (tid == 1023) g_medge[blk] = (int)in[1023];
    unsigned base = in[tid] - part[tid];
    for (int k = 0; k < PER; ++k) {
        int idx = tid * PER + k;
        if (idx < NBUCK) { cur[idx] = base; base += c[idx]; }
    }
    __syncthreads();

    size_t gbase = (size_t)blk * CAP;
    const int NIT = (NPB + 31) / 32;         // 11
    for (int it = 0; it < NIT; ++it) {
        int li = it * 32 + wid;
        int i = blk * NPB + li;
        bool act = (li < NPB && i < NN);
        int d = act ? g_deg[i] : 0;
        unsigned lo = act ? g_lofs[i] : 0u;
        const uint4* te = &g_tmpE[(size_t)(act ? i : 0) * MAXDEG];

        unsigned key[6]; unsigned srcv[6]; unsigned wbits[6];
        #pragma unroll
        for (int cch = 0; cch < 6; ++cch) {
            int s = cch * 32 + lane;
            if (s < d) {
                uint4 u4 = te[s];
                srcv[cch] = u4.x; wbits[cch] = u4.y; key[cch] = u4.z;
            } else {
                key[cch] = 0xFFFFFFFFu; srcv[cch] = 0u; wbits[cch] = 0u;
            }
        }
        int rank[6] = {0, 0, 0, 0, 0, 0};
        int nch = (d + 31) >> 5;             // uniform per warp
        #pragma unroll
        for (int c2 = 0; c2 < 6; ++c2) {
            if (c2 < nch) {
                unsigned kc = key[c2];
                #pragma unroll
                for (int l = 0; l < 32; ++l) {
                    unsigned kj = __shfl_sync(0xFFFFFFFFu, kc, l);
                    if (kj != 0xFFFFFFFFu) {
                        #pragma unroll
                        for (int cch = 0; cch < 6; ++cch)
                            rank[cch] += (kj < key[cch]) ? 1 : 0;
                    }
                }
            }
        }
        #pragma unroll
        for (int cch = 0; cch < 6; ++cch) {
            int s = cch * 32 + lane;
            if (s < d) {
                unsigned pos = lo + (unsigned)rank[cch];
                unsigned idx = atomicAdd(&cur[srcv[cch] >> 6], 1u);
                if (idx < CAP && pos < CAP) {
                    GEnt g; g.packed = (srcv[cch] << 15) | pos;
                    g.w = __uint_as_float(wbits[cch]);
                    g_g[gbase + idx] = g;
                }
            }
        }
    }
}

// ---------------- launches 4..103: fused simulation step ----------------
__global__ void __launch_bounds__(TPB) step_k(
    int t, int parity,
    unsigned kn0, unsigned kn1, unsigned kf0, unsigned kf1)
{
    extern __shared__ float sval[];          // CAP floats = 96KB
    int blk = blockIdx.x;
    const float* actIn  = parity ? g_actB : g_actA;
    float*       actOut = parity ? g_actA : g_actB;
    int mpad = g_m[blk];
    int me   = g_medge[blk];
    bool staged = (mpad <= CAP && me <= CAP);

    if (staged) {
        const GEnt* gl = &g_g[(size_t)blk * CAP];
        for (int j = threadIdx.x; j < me; j += TPB) {
            GEnt g = gl[j];
            sval[g.packed & 0x7FFFu] =
                __fmul_rn(g.w, __ldg(&actIn[g.packed >> 15]));
        }
    }
    __syncthreads();

    int li = threadIdx.x;
    int i = blk * NPB + li;
    if (li < NPB && i < NN) {
        float acc = 0.0f;
        int d = g_deg[i];
        if (staged) {
            unsigned lo = g_lofs[i];
            #pragma unroll 8
            for (int s = 0; s < d; ++s)
                acc = __fadd_rn(acc, sval[lo + s]);          // eid-ordered chain
        } else {
            // never-taken safety net: selection by min eid over raw records
            const uint4* te = &g_tmpE[(size_t)i * MAXDEG];
            unsigned done[6] = {0, 0, 0, 0, 0, 0};
            for (int r = 0; r < d; ++r) {
                unsigned bestk = 0xFFFFFFFFu; int bs = 0;
                unsigned bsrc = 0, bw = 0;
                for (int s = 0; s < d; ++s) {
                    if (done[s >> 5] & (1u << (s & 31))) continue;
                    uint4 u4 = te[s];
                    if (u4.z < bestk) { bestk = u4.z; bs = s; bsrc = u4.x; bw = u4.y; }
                }
                done[bs >> 5] |= 1u << (bs & 31);
                acc = __fadd_rn(acc,
                    __fmul_rn(__uint_as_float(bw), __ldg(&actIn[bsrc])));
            }
        }

        unsigned b0, b1;
        tf2x32(kf0, kf1, 0u, (unsigned)i, b0, b1);
        unsigned fb = b0 ^ b1;
        unsigned thr = g_thr;
        bool filt = (thr != 0xFFFFFFFFu) ? ((fb >> 9) >= thr)
                                         : (bits_to_normal(fb) > 1.5f);
        float l;
        if (filt) {
            tf2x32(kn0, kn1, 0u, (unsigned)i, b0, b1);
            float noise = __fmul_rn(0.3f, bits_to_normal(b0 ^ b1));
            l = __fadd_rn(__fmul_rn(0.025f, acc),
                          __fmul_rn(0.001f, __fadd_rn(1.0f, noise)));
        } else {
            l = __fadd_rn(__fmul_rn(0.025f, acc), 0.001f);
        }
        float spike = (l > 0.001378f) ? 1.0f : 0.0f;
        float na = __fsub_rn(__fadd_rn(acc, spike),
                             __fmul_rn(__fdiv_rn(acc, 0.01f), 1e-4f));
        g_spk[(size_t)t * NN + i] = spike;
        actOut[i] = na;
    }
}

// ---------------- last launch: [t][i] -> [i][t] transpose ----------------
__global__ void trans_k(float* __restrict__ out)
{
    __shared__ float tile[32][33];
    int i0 = blockIdx.x * 32, t0 = blockIdx.y * 32;
    int tr = t0 + threadIdx.y, ic = i0 + threadIdx.x;
    tile[threadIdx.y][threadIdx.x] =
        (tr < NSTEPS && ic < NN) ? g_spk[(size_t)tr * NN + ic] : 0.0f;
    __syncthreads();
    int iw = i0 + threadIdx.y, tw = t0 + threadIdx.x;
    if (iw < NN && tw < NSTEPS)
        out[(size_t)iw * NSTEPS + tw] = tile[threadIdx.x][threadIdx.y];
}

// ---------------- host ----------------
extern "C" void kernel_launch(void* const* d_in, const int* in_sizes, int n_in,
                              void* d_out, int out_size)
{
    const float* act0 = (const float*)d_in[0];
    const float* W    = (const float*)d_in[1];
    const void*  ei   = d_in[2];
    float*       out  = (float*)d_out;

    cudaFuncSetAttribute(step_k, cudaFuncAttributeMaxDynamicSharedMemorySize,
                         CAP * (int)sizeof(float));

    {
        size_t zn = (size_t)NB * NBUCK;
        prep_zero<<<(int)((zn + 255) / 256), 256>>>(ei);           // launch 0
    }
    prep_scatter <<<(EE + 255) / 256, 256>>>(ei, W);               // launch 1
    prep_csr     <<<NB, TPB>>>(act0);                              // launch 2
    prep_rankfill<<<NB, 1024>>>();                                 // launch 3

    for (int t = 0; t < NSTEPS; ++t) {                             // launch 4 = step 0
        unsigned kt0, kt1, n0, n1, f0, f1;
        tf2x32(0u, 42u, 0u, (unsigned)t, kt0, kt1);
        tf2x32(kt0, kt1, 0u, 0u, n0, n1);
        tf2x32(kt0, kt1, 0u, 1u, f0, f1);
        step_k<<<NB, TPB, CAP * sizeof(float)>>>(t, t & 1, n0, n1, f0, f1);
    }
    trans_k<<<dim3((NN + 31) / 32, (NSTEPS + 31) / 32), dim3(32, 32)>>>(out);
}